// round 5
// baseline (speedup 1.0000x reference)
#include <cuda_runtime.h>
#include <math_constants.h>

// x/bias/a/b : [4,128,128,256] f32 NHWC; 2x2/2 argmax-pool of x, gather from
// all 4 tensors at the argmax, plus global truncation-interval reduction.
// d_out: out_x | out_bias | out_a | out_b | l | u (flattened).
namespace {
constexpr int Hh = 128, Ww = 128, Cc = 256, Hp = 64, Wp = 64;
constexpr int NOUT = 4 * Hp * Wp * Cc;    // 4,194,304 per output tensor
constexpr int N2   = NOUT / 2;            // 2,097,152 vec2 outputs
constexpr int C2   = Cc / 2;              // 128 (float2 units along C)
constexpr int WC2  = Ww * C2;             // 16384
constexpr int SCAL = 4 * NOUT;            // scalar slots: l, u
constexpr int NBLK = N2 / 256;            // 8192 blocks
}

// Scratch for single-kernel tail reduction (no allocs allowed -> device globals).
__device__ float        g_partials[NBLK * 2];
__device__ unsigned int g_count = 0;

__device__ __forceinline__ float getc(const float2& v, int k) { return k == 0 ? v.x : v.y; }
__device__ __forceinline__ void  setc(float2& v, int k, float f) { if (k == 0) v.x = f; else v.y = f; }
__device__ __forceinline__ float sel4(float v0, float v1, float v2, float v3, int k) {
    return k == 0 ? v0 : (k == 1 ? v1 : (k == 2 ? v2 : v3));
}

__global__ void __launch_bounds__(256, 8)
pool_kernel(const float2* __restrict__ x,
            const float2* __restrict__ bias,
            const float2* __restrict__ a,
            const float2* __restrict__ b,
            const float* __restrict__ lin,
            const float* __restrict__ uin,
            float* __restrict__ out) {
    float2* __restrict__ out2 = reinterpret_cast<float2*>(out);

    const int i = blockIdx.x * 256 + threadIdx.x;   // exactly N2 threads
    // i = (((bb*Hp + hp)*Wp + wp)*C2 + c2)
    int c2 = i & (C2 - 1);
    int t  = i >> 7;            // C2 == 128
    int wp = t & (Wp - 1);
    t >>= 6;
    int hp = t & (Hp - 1);
    int bb = t >> 6;
    const int base = ((bb * Hh + 2 * hp) * Ww + 2 * wp) * C2 + c2;
    // Window order matches reference patches: (0,0),(0,1),(1,0),(1,1)
    const int o1 = C2, o2 = WC2, o3 = WC2 + C2;

    // ---- Phase 1: x -> argmax + out_x ----
    const float2 X0 = __ldcs(x + base), X1 = __ldcs(x + base + o1),
                 X2 = __ldcs(x + base + o2), X3 = __ldcs(x + base + o3);
    int idx[2];
    float2 ox;
    #pragma unroll
    for (int ln = 0; ln < 2; ln++) {
        float v0 = getc(X0, ln), v1 = getc(X1, ln), v2 = getc(X2, ln), v3 = getc(X3, ln);
        int k = 0; float best = v0;                       // first-max (strict >)
        if (v1 > best) { best = v1; k = 1; }
        if (v2 > best) { best = v2; k = 2; }
        if (v3 > best) { best = v3; k = 3; }
        idx[ln] = k;
        setc(ox, ln, best);
    }
    __stcs(out2 + i, ox);

    // ---- Phase 2: bias -> out_bias + partial noms (bis - bi_j) ----
    const float2 I0 = __ldcs(bias + base), I1 = __ldcs(bias + base + o1),
                 I2 = __ldcs(bias + base + o2), I3 = __ldcs(bias + base + o3);
    float nb[2][4];
    float2 obi;
    #pragma unroll
    for (int ln = 0; ln < 2; ln++) {
        float v0 = getc(I0, ln), v1 = getc(I1, ln), v2 = getc(I2, ln), v3 = getc(I3, ln);
        float s = sel4(v0, v1, v2, v3, idx[ln]);
        setc(obi, ln, s);
        nb[ln][0] = s - v0; nb[ln][1] = s - v1; nb[ln][2] = s - v2; nb[ln][3] = s - v3;
    }
    __stcs(out2 + N2 + i, obi);

    // ---- Phase 3: a -> out_a + full noms (nb + (as - a_j)) ----
    const float2 A0 = __ldcs(a + base), A1 = __ldcs(a + base + o1),
                 A2 = __ldcs(a + base + o2), A3 = __ldcs(a + base + o3);
    float2 oa;
    #pragma unroll
    for (int ln = 0; ln < 2; ln++) {
        float v0 = getc(A0, ln), v1 = getc(A1, ln), v2 = getc(A2, ln), v3 = getc(A3, ln);
        float s = sel4(v0, v1, v2, v3, idx[ln]);
        setc(oa, ln, s);
        nb[ln][0] += s - v0; nb[ln][1] += s - v1; nb[ln][2] += s - v2; nb[ln][3] += s - v3;
    }
    __stcs(out2 + 2 * N2 + i, oa);

    // ---- Phase 4: b -> out_b + interval candidates (branchless) ----
    float lloc = -CUDART_INF_F;
    float uloc =  CUDART_INF_F;
    const float2 B0 = __ldcs(b + base), B1 = __ldcs(b + base + o1),
                 B2 = __ldcs(b + base + o2), B3 = __ldcs(b + base + o3);
    float2 ob;
    #pragma unroll
    for (int ln = 0; ln < 2; ln++) {
        float v0 = getc(B0, ln), v1 = getc(B1, ln), v2 = getc(B2, ln), v3 = getc(B3, ln);
        float s = sel4(v0, v1, v2, v3, idx[ln]);
        setc(ob, ln, s);
        float d[4] = { v0 - s, v1 - s, v2 - s, v3 - s };
        #pragma unroll
        for (int j = 0; j < 4; j++) {
            // j==idx: 0/0 -> NaN, but both guards are false, so never used.
            float q = __fdividef(nb[ln][j], d[j]);
            uloc = (d[j] > 0.0f) ? fminf(uloc, q) : uloc;
            lloc = (d[j] < 0.0f) ? fmaxf(lloc, q) : lloc;
        }
    }
    __stcs(out2 + 3 * N2 + i, ob);

    // ---- Block reduction: warp shuffle -> shared -> per-block partial ----
    #pragma unroll
    for (int off = 16; off; off >>= 1) {
        lloc = fmaxf(lloc, __shfl_xor_sync(0xffffffffu, lloc, off));
        uloc = fminf(uloc, __shfl_xor_sync(0xffffffffu, uloc, off));
    }
    __shared__ float sl[8], su[8];
    __shared__ bool  s_last;
    const int warp = threadIdx.x >> 5;
    const int lane = threadIdx.x & 31;
    if (lane == 0) { sl[warp] = lloc; su[warp] = uloc; }
    __syncthreads();
    if (threadIdx.x == 0) {
        float lb = sl[0], ub = su[0];
        #pragma unroll
        for (int w = 1; w < 8; w++) {
            lb = fmaxf(lb, sl[w]);
            ub = fminf(ub, su[w]);
        }
        g_partials[2 * blockIdx.x]     = lb;
        g_partials[2 * blockIdx.x + 1] = ub;
        __threadfence();
        s_last = (atomicAdd(&g_count, 1u) == (unsigned)(NBLK - 1));
    }
    __syncthreads();

    // ---- Tail: last block reduces all partials + clamps with l/u inputs ----
    if (s_last) {
        float lb = -CUDART_INF_F, ub = CUDART_INF_F;
        for (int p = threadIdx.x; p < NBLK; p += 256) {
            lb = fmaxf(lb, g_partials[2 * p]);
            ub = fminf(ub, g_partials[2 * p + 1]);
        }
        #pragma unroll
        for (int off = 16; off; off >>= 1) {
            lb = fmaxf(lb, __shfl_xor_sync(0xffffffffu, lb, off));
            ub = fminf(ub, __shfl_xor_sync(0xffffffffu, ub, off));
        }
        if (lane == 0) { sl[warp] = lb; su[warp] = ub; }
        __syncthreads();
        if (threadIdx.x == 0) {
            float lf = sl[0], uf = su[0];
            #pragma unroll
            for (int w = 1; w < 8; w++) {
                lf = fmaxf(lf, sl[w]);
                uf = fminf(uf, su[w]);
            }
            out[SCAL]     = fmaxf(lin[0], lf);
            out[SCAL + 1] = fminf(uin[0], uf);
            g_count = 0;   // reset for next graph replay (deterministic)
        }
    }
}

extern "C" void kernel_launch(void* const* d_in, const int* in_sizes, int n_in,
                              void* d_out, int out_size) {
    const float2* x  = (const float2*)d_in[0];
    const float2* bi = (const float2*)d_in[1];
    const float2* a  = (const float2*)d_in[2];
    const float2* b  = (const float2*)d_in[3];
    const float*  l  = (const float*)d_in[4];
    const float*  u  = (const float*)d_in[5];
    float* out = (float*)d_out;

    pool_kernel<<<NBLK, 256>>>(x, bi, a, b, l, u, out);   // single kernel
}

// round 6
// speedup vs baseline: 1.0289x; 1.0289x over previous
#include <cuda_runtime.h>
#include <math_constants.h>

// x/bias/a/b : [4,128,128,256] f32 NHWC; 2x2/2 argmax-pool of x, gather from
// all 4 tensors at the argmax, plus global truncation-interval reduction.
// d_out: out_x | out_bias | out_a | out_b | l | u (flattened).
namespace {
constexpr int Hh = 128, Ww = 128, Cc = 256, Hp = 64, Wp = 64;
constexpr int NOUT = 4 * Hp * Wp * Cc;    // 4,194,304 per output tensor
constexpr int N2   = NOUT / 2;            // 2,097,152 vec2 outputs
constexpr int C2   = Cc / 2;              // 128 (float2 units along C)
constexpr int WC2  = Ww * C2;             // 16384
constexpr int SCAL = 4 * NOUT;            // scalar slots: l, u
constexpr int NBLK = N2 / 256;            // 8192 blocks
}

// Global reduction lattice (statically seeded; last block resets for replay).
// -inf = 0xFF800000, +inf = 0x7F800000.
__device__ unsigned int g_lbits = 0xFF800000u;   // running max (lower bound cand.)
__device__ unsigned int g_ubits = 0x7F800000u;   // running min (upper bound cand.)
__device__ unsigned int g_count = 0;

__device__ __forceinline__ float getc(const float2& v, int k) { return k == 0 ? v.x : v.y; }
__device__ __forceinline__ void  setc(float2& v, int k, float f) { if (k == 0) v.x = f; else v.y = f; }
__device__ __forceinline__ float sel4(float v0, float v1, float v2, float v3, int k) {
    return k == 0 ? v0 : (k == 1 ? v1 : (k == 2 ? v2 : v3));
}

// Exact float max/min atomics via sign-aware integer ordering.
__device__ __forceinline__ void atomicMaxF(unsigned int* addr, float v) {
    if (v >= 0.0f) atomicMax((int*)addr, __float_as_int(v));
    else           atomicMin(addr, __float_as_uint(v));
}
__device__ __forceinline__ void atomicMinF(unsigned int* addr, float v) {
    if (v >= 0.0f) atomicMin((int*)addr, __float_as_int(v));
    else           atomicMax(addr, __float_as_uint(v));
}

__global__ void __launch_bounds__(256, 8)
pool_kernel(const float2* __restrict__ x,
            const float2* __restrict__ bias,
            const float2* __restrict__ a,
            const float2* __restrict__ b,
            const float* __restrict__ lin,
            const float* __restrict__ uin,
            float* __restrict__ out) {
    float2* __restrict__ out2 = reinterpret_cast<float2*>(out);

    const int i = blockIdx.x * 256 + threadIdx.x;   // exactly N2 threads
    // i = (((bb*Hp + hp)*Wp + wp)*C2 + c2)
    int c2 = i & (C2 - 1);
    int t  = i >> 7;            // C2 == 128
    int wp = t & (Wp - 1);
    t >>= 6;
    int hp = t & (Hp - 1);
    int bb = t >> 6;
    const int base = ((bb * Hh + 2 * hp) * Ww + 2 * wp) * C2 + c2;
    // Window order matches reference patches: (0,0),(0,1),(1,0),(1,1)
    const int o1 = C2, o2 = WC2, o3 = WC2 + C2;

    // ---- Phase 1: x -> argmax + out_x ----
    const float2 X0 = __ldcs(x + base), X1 = __ldcs(x + base + o1),
                 X2 = __ldcs(x + base + o2), X3 = __ldcs(x + base + o3);
    int idx[2];
    float2 ox;
    #pragma unroll
    for (int ln = 0; ln < 2; ln++) {
        float v0 = getc(X0, ln), v1 = getc(X1, ln), v2 = getc(X2, ln), v3 = getc(X3, ln);
        int k = 0; float best = v0;                       // first-max (strict >)
        if (v1 > best) { best = v1; k = 1; }
        if (v2 > best) { best = v2; k = 2; }
        if (v3 > best) { best = v3; k = 3; }
        idx[ln] = k;
        setc(ox, ln, best);
    }
    __stcs(out2 + i, ox);

    // ---- Phase 2: bias -> out_bias + partial noms (bis - bi_j) ----
    const float2 I0 = __ldcs(bias + base), I1 = __ldcs(bias + base + o1),
                 I2 = __ldcs(bias + base + o2), I3 = __ldcs(bias + base + o3);
    float nb[2][4];
    float2 obi;
    #pragma unroll
    for (int ln = 0; ln < 2; ln++) {
        float v0 = getc(I0, ln), v1 = getc(I1, ln), v2 = getc(I2, ln), v3 = getc(I3, ln);
        float s = sel4(v0, v1, v2, v3, idx[ln]);
        setc(obi, ln, s);
        nb[ln][0] = s - v0; nb[ln][1] = s - v1; nb[ln][2] = s - v2; nb[ln][3] = s - v3;
    }
    __stcs(out2 + N2 + i, obi);

    // ---- Phase 3: a -> out_a + full noms (nb + (as - a_j)) ----
    const float2 A0 = __ldcs(a + base), A1 = __ldcs(a + base + o1),
                 A2 = __ldcs(a + base + o2), A3 = __ldcs(a + base + o3);
    float2 oa;
    #pragma unroll
    for (int ln = 0; ln < 2; ln++) {
        float v0 = getc(A0, ln), v1 = getc(A1, ln), v2 = getc(A2, ln), v3 = getc(A3, ln);
        float s = sel4(v0, v1, v2, v3, idx[ln]);
        setc(oa, ln, s);
        nb[ln][0] += s - v0; nb[ln][1] += s - v1; nb[ln][2] += s - v2; nb[ln][3] += s - v3;
    }
    __stcs(out2 + 2 * N2 + i, oa);

    // ---- Phase 4: b -> out_b + interval candidates (branchless) ----
    float lloc = -CUDART_INF_F;
    float uloc =  CUDART_INF_F;
    const float2 B0 = __ldcs(b + base), B1 = __ldcs(b + base + o1),
                 B2 = __ldcs(b + base + o2), B3 = __ldcs(b + base + o3);
    float2 ob;
    #pragma unroll
    for (int ln = 0; ln < 2; ln++) {
        float v0 = getc(B0, ln), v1 = getc(B1, ln), v2 = getc(B2, ln), v3 = getc(B3, ln);
        float s = sel4(v0, v1, v2, v3, idx[ln]);
        setc(ob, ln, s);
        float d[4] = { v0 - s, v1 - s, v2 - s, v3 - s };
        #pragma unroll
        for (int j = 0; j < 4; j++) {
            // j==idx: 0/0 -> NaN, but both guards are false, so never used.
            float q = __fdividef(nb[ln][j], d[j]);
            uloc = (d[j] > 0.0f) ? fminf(uloc, q) : uloc;
            lloc = (d[j] < 0.0f) ? fmaxf(lloc, q) : lloc;
        }
    }
    __stcs(out2 + 3 * N2 + i, ob);

    // ---- Block reduction: warp shuffle -> shared -> 2 global atomics ----
    #pragma unroll
    for (int off = 16; off; off >>= 1) {
        lloc = fmaxf(lloc, __shfl_xor_sync(0xffffffffu, lloc, off));
        uloc = fminf(uloc, __shfl_xor_sync(0xffffffffu, uloc, off));
    }
    __shared__ float sl[8], su[8];
    const int warp = threadIdx.x >> 5;
    const int lane = threadIdx.x & 31;
    if (lane == 0) { sl[warp] = lloc; su[warp] = uloc; }
    __syncthreads();
    if (threadIdx.x == 0) {
        float lb = sl[0], ub = su[0];
        #pragma unroll
        for (int w = 1; w < 8; w++) {
            lb = fmaxf(lb, sl[w]);
            ub = fminf(ub, su[w]);
        }
        if (lb != -CUDART_INF_F) atomicMaxF(&g_lbits, lb);
        if (ub !=  CUDART_INF_F) atomicMinF(&g_ubits, ub);
        __threadfence();   // order lattice updates before arrival
        if (atomicAdd(&g_count, 1u) == (unsigned)(NBLK - 1)) {
            // Last block: finalize the two scalars, reset lattice for replay.
            float lf = __uint_as_float(*(volatile unsigned int*)&g_lbits);
            float uf = __uint_as_float(*(volatile unsigned int*)&g_ubits);
            out[SCAL]     = fmaxf(lin[0], lf);
            out[SCAL + 1] = fminf(uin[0], uf);
            g_lbits = 0xFF800000u;
            g_ubits = 0x7F800000u;
            __threadfence();
            g_count = 0;
        }
    }
}

extern "C" void kernel_launch(void* const* d_in, const int* in_sizes, int n_in,
                              void* d_out, int out_size) {
    const float2* x  = (const float2*)d_in[0];
    const float2* bi = (const float2*)d_in[1];
    const float2* a  = (const float2*)d_in[2];
    const float2* b  = (const float2*)d_in[3];
    const float*  l  = (const float*)d_in[4];
    const float*  u  = (const float*)d_in[5];
    float* out = (float*)d_out;

    pool_kernel<<<NBLK, 256>>>(x, bi, a, b, l, u, out);   // single kernel
}

// round 7
// speedup vs baseline: 1.0407x; 1.0115x over previous
#include <cuda_runtime.h>
#include <math_constants.h>

// x/bias/a/b : [4,128,128,256] f32 NHWC; 2x2/2 argmax-pool of x, gather from
// all 4 tensors at the argmax, plus global truncation-interval reduction.
// d_out: out_x | out_bias | out_a | out_b | l | u (flattened).
namespace {
constexpr int Hh = 128, Ww = 128, Cc = 256, Hp = 64, Wp = 64;
constexpr int NOUT = 4 * Hp * Wp * Cc;    // 4,194,304 per output tensor
constexpr int N2   = NOUT / 2;            // 2,097,152 vec2 outputs
constexpr int C2   = Cc / 2;              // 128 (float2 units along C)
constexpr int WC2  = Ww * C2;             // 16384
constexpr int SCAL = 4 * NOUT;            // scalar slots: l, u
constexpr int NBLK = N2 / 256;            // 8192 blocks
}

// Global reduction lattice (statically seeded; last block resets for replay).
// -inf = 0xFF800000, +inf = 0x7F800000.
__device__ unsigned int g_lbits = 0xFF800000u;   // running max (lower bound cand.)
__device__ unsigned int g_ubits = 0x7F800000u;   // running min (upper bound cand.)
__device__ unsigned int g_count = 0;

__device__ __forceinline__ float getc(const float2& v, int k) { return k == 0 ? v.x : v.y; }
__device__ __forceinline__ void  setc(float2& v, int k, float f) { if (k == 0) v.x = f; else v.y = f; }
__device__ __forceinline__ float sel4(float v0, float v1, float v2, float v3, int k) {
    return k == 0 ? v0 : (k == 1 ? v1 : (k == 2 ? v2 : v3));
}

// Exact float max/min atomics via sign-aware integer ordering (relaxed).
__device__ __forceinline__ void atomicMaxF(unsigned int* addr, float v) {
    if (v >= 0.0f) atomicMax((int*)addr, __float_as_int(v));
    else           atomicMin(addr, __float_as_uint(v));
}
__device__ __forceinline__ void atomicMinF(unsigned int* addr, float v) {
    if (v >= 0.0f) atomicMin((int*)addr, __float_as_int(v));
    else           atomicMax(addr, __float_as_uint(v));
}

// Counter arrival with acq_rel ordering — orders this block's prior lattice
// atomics before the arrival (release), and makes all earlier blocks' lattice
// updates visible to the last arriver (acquire). No CCTL.IVALL / L1 flush.
__device__ __forceinline__ unsigned int arrive_acq_rel(unsigned int* ctr) {
    unsigned int old;
    asm volatile("atom.acq_rel.gpu.global.add.u32 %0, [%1], %2;"
                 : "=r"(old) : "l"(ctr), "r"(1u) : "memory");
    return old;
}

__global__ void __launch_bounds__(256, 8)
pool_kernel(const float2* __restrict__ x,
            const float2* __restrict__ bias,
            const float2* __restrict__ a,
            const float2* __restrict__ b,
            const float* __restrict__ lin,
            const float* __restrict__ uin,
            float* __restrict__ out) {
    float2* __restrict__ out2 = reinterpret_cast<float2*>(out);

    const int i = blockIdx.x * 256 + threadIdx.x;   // exactly N2 threads
    // i = (((bb*Hp + hp)*Wp + wp)*C2 + c2)
    int c2 = i & (C2 - 1);
    int t  = i >> 7;            // C2 == 128
    int wp = t & (Wp - 1);
    t >>= 6;
    int hp = t & (Hp - 1);
    int bb = t >> 6;
    const int base = ((bb * Hh + 2 * hp) * Ww + 2 * wp) * C2 + c2;
    // Window order matches reference patches: (0,0),(0,1),(1,0),(1,1)
    const int o1 = C2, o2 = WC2, o3 = WC2 + C2;

    // ---- Phase 1: x -> argmax + out_x ----
    const float2 X0 = __ldcs(x + base), X1 = __ldcs(x + base + o1),
                 X2 = __ldcs(x + base + o2), X3 = __ldcs(x + base + o3);
    int idx[2];
    float2 ox;
    #pragma unroll
    for (int ln = 0; ln < 2; ln++) {
        float v0 = getc(X0, ln), v1 = getc(X1, ln), v2 = getc(X2, ln), v3 = getc(X3, ln);
        int k = 0; float best = v0;                       // first-max (strict >)
        if (v1 > best) { best = v1; k = 1; }
        if (v2 > best) { best = v2; k = 2; }
        if (v3 > best) { best = v3; k = 3; }
        idx[ln] = k;
        setc(ox, ln, best);
    }
    __stcs(out2 + i, ox);

    // ---- Phase 2: bias -> out_bias + partial noms (bis - bi_j) ----
    const float2 I0 = __ldcs(bias + base), I1 = __ldcs(bias + base + o1),
                 I2 = __ldcs(bias + base + o2), I3 = __ldcs(bias + base + o3);
    float nb[2][4];
    float2 obi;
    #pragma unroll
    for (int ln = 0; ln < 2; ln++) {
        float v0 = getc(I0, ln), v1 = getc(I1, ln), v2 = getc(I2, ln), v3 = getc(I3, ln);
        float s = sel4(v0, v1, v2, v3, idx[ln]);
        setc(obi, ln, s);
        nb[ln][0] = s - v0; nb[ln][1] = s - v1; nb[ln][2] = s - v2; nb[ln][3] = s - v3;
    }
    __stcs(out2 + N2 + i, obi);

    // ---- Phase 3: a -> out_a + full noms (nb + (as - a_j)) ----
    const float2 A0 = __ldcs(a + base), A1 = __ldcs(a + base + o1),
                 A2 = __ldcs(a + base + o2), A3 = __ldcs(a + base + o3);
    float2 oa;
    #pragma unroll
    for (int ln = 0; ln < 2; ln++) {
        float v0 = getc(A0, ln), v1 = getc(A1, ln), v2 = getc(A2, ln), v3 = getc(A3, ln);
        float s = sel4(v0, v1, v2, v3, idx[ln]);
        setc(oa, ln, s);
        nb[ln][0] += s - v0; nb[ln][1] += s - v1; nb[ln][2] += s - v2; nb[ln][3] += s - v3;
    }
    __stcs(out2 + 2 * N2 + i, oa);

    // ---- Phase 4: b -> out_b + interval candidates (branchless) ----
    float lloc = -CUDART_INF_F;
    float uloc =  CUDART_INF_F;
    const float2 B0 = __ldcs(b + base), B1 = __ldcs(b + base + o1),
                 B2 = __ldcs(b + base + o2), B3 = __ldcs(b + base + o3);
    float2 ob;
    #pragma unroll
    for (int ln = 0; ln < 2; ln++) {
        float v0 = getc(B0, ln), v1 = getc(B1, ln), v2 = getc(B2, ln), v3 = getc(B3, ln);
        float s = sel4(v0, v1, v2, v3, idx[ln]);
        setc(ob, ln, s);
        float d[4] = { v0 - s, v1 - s, v2 - s, v3 - s };
        #pragma unroll
        for (int j = 0; j < 4; j++) {
            // j==idx: 0/0 -> NaN, but both guards are false, so never used.
            float q = __fdividef(nb[ln][j], d[j]);
            uloc = (d[j] > 0.0f) ? fminf(uloc, q) : uloc;
            lloc = (d[j] < 0.0f) ? fmaxf(lloc, q) : lloc;
        }
    }
    __stcs(out2 + 3 * N2 + i, ob);

    // ---- Block reduction: warp shuffle -> shared -> 2 global atomics ----
    #pragma unroll
    for (int off = 16; off; off >>= 1) {
        lloc = fmaxf(lloc, __shfl_xor_sync(0xffffffffu, lloc, off));
        uloc = fminf(uloc, __shfl_xor_sync(0xffffffffu, uloc, off));
    }
    __shared__ float sl[8], su[8];
    const int warp = threadIdx.x >> 5;
    const int lane = threadIdx.x & 31;
    if (lane == 0) { sl[warp] = lloc; su[warp] = uloc; }
    __syncthreads();
    if (threadIdx.x == 0) {
        float lb = sl[0], ub = su[0];
        #pragma unroll
        for (int w = 1; w < 8; w++) {
            lb = fmaxf(lb, sl[w]);
            ub = fminf(ub, su[w]);
        }
        if (lb != -CUDART_INF_F) atomicMaxF(&g_lbits, lb);
        if (ub !=  CUDART_INF_F) atomicMinF(&g_ubits, ub);
        // acq_rel arrival replaces __threadfence() — no L1D flush in hot path.
        if (arrive_acq_rel(&g_count) == (unsigned)(NBLK - 1)) {
            // Last block: finalize the two scalars, reset lattice for replay.
            float lf = __uint_as_float(*(volatile unsigned int*)&g_lbits);
            float uf = __uint_as_float(*(volatile unsigned int*)&g_ubits);
            out[SCAL]     = fmaxf(lin[0], lf);
            out[SCAL + 1] = fminf(uin[0], uf);
            // Reset for next graph replay; visibility guaranteed by the
            // kernel-launch boundary (single finalize runs once per launch).
            *(volatile unsigned int*)&g_lbits = 0xFF800000u;
            *(volatile unsigned int*)&g_ubits = 0x7F800000u;
            __threadfence();              // once per launch — negligible
            *(volatile unsigned int*)&g_count = 0u;
        }
    }
}

extern "C" void kernel_launch(void* const* d_in, const int* in_sizes, int n_in,
                              void* d_out, int out_size) {
    const float2* x  = (const float2*)d_in[0];
    const float2* bi = (const float2*)d_in[1];
    const float2* a  = (const float2*)d_in[2];
    const float2* b  = (const float2*)d_in[3];
    const float*  l  = (const float*)d_in[4];
    const float*  u  = (const float*)d_in[5];
    float* out = (float*)d_out;

    pool_kernel<<<NBLK, 256>>>(x, bi, a, b, l, u, out);   // single kernel
}

// round 8
// speedup vs baseline: 1.0804x; 1.0381x over previous
#include <cuda_runtime.h>
#include <math_constants.h>

// x/bias/a/b : [4,128,128,256] f32 NHWC; 2x2/2 argmax-pool of x, gather from
// all 4 tensors at the argmax, plus global truncation-interval reduction.
// d_out: out_x | out_bias | out_a | out_b | l | u (flattened).
namespace {
constexpr int Hh = 128, Ww = 128, Cc = 256, Hp = 64, Wp = 64;
constexpr int NOUT = 4 * Hp * Wp * Cc;    // 4,194,304 per output tensor
constexpr int N2   = NOUT / 2;            // 2,097,152 vec2 outputs
constexpr int C2   = Cc / 2;              // 128 (float2 units along C)
constexpr int WC2  = Ww * C2;             // 16384
constexpr int SCAL = 4 * NOUT;            // scalar slots: l, u
constexpr int NBLK = N2 / 256;            // 8192 blocks
}

// Global reduction lattice (statically seeded; finalizer resets for replay).
// All accesses are L2 atomics (RMW) -> coherent without fences.
// -inf = 0xFF800000, +inf = 0x7F800000.
__device__ unsigned int g_lbits = 0xFF800000u;   // running max (lower bound cand.)
__device__ unsigned int g_ubits = 0x7F800000u;   // running min (upper bound cand.)
__device__ unsigned int g_count = 0;

__device__ __forceinline__ float getc(const float2& v, int k) { return k == 0 ? v.x : v.y; }
__device__ __forceinline__ void  setc(float2& v, int k, float f) { if (k == 0) v.x = f; else v.y = f; }
__device__ __forceinline__ float sel4(float v0, float v1, float v2, float v3, int k) {
    return k == 0 ? v0 : (k == 1 ? v1 : (k == 2 ? v2 : v3));
}

// Exact float max/min atomics via sign-aware integer ordering (relaxed).
__device__ __forceinline__ void atomicMaxF(unsigned int* addr, float v) {
    if (v >= 0.0f) atomicMax((int*)addr, __float_as_int(v));
    else           atomicMin(addr, __float_as_uint(v));
}
__device__ __forceinline__ void atomicMinF(unsigned int* addr, float v) {
    if (v >= 0.0f) atomicMin((int*)addr, __float_as_int(v));
    else           atomicMax(addr, __float_as_uint(v));
}

__global__ void __launch_bounds__(256, 8)
pool_kernel(const float2* __restrict__ x,
            const float2* __restrict__ bias,
            const float2* __restrict__ a,
            const float2* __restrict__ b,
            const float* __restrict__ lin,
            const float* __restrict__ uin,
            float* __restrict__ out) {
    float2* __restrict__ out2 = reinterpret_cast<float2*>(out);

    const int i = blockIdx.x * 256 + threadIdx.x;   // exactly N2 threads
    // i = (((bb*Hp + hp)*Wp + wp)*C2 + c2)
    int c2 = i & (C2 - 1);
    int t  = i >> 7;            // C2 == 128
    int wp = t & (Wp - 1);
    t >>= 6;
    int hp = t & (Hp - 1);
    int bb = t >> 6;
    const int base = ((bb * Hh + 2 * hp) * Ww + 2 * wp) * C2 + c2;
    // Window order matches reference patches: (0,0),(0,1),(1,0),(1,1)
    const int o1 = C2, o2 = WC2, o3 = WC2 + C2;

    // ---- Phase 1: x -> argmax + out_x ----
    const float2 X0 = __ldcs(x + base), X1 = __ldcs(x + base + o1),
                 X2 = __ldcs(x + base + o2), X3 = __ldcs(x + base + o3);
    int idx[2];
    float2 ox;
    #pragma unroll
    for (int ln = 0; ln < 2; ln++) {
        float v0 = getc(X0, ln), v1 = getc(X1, ln), v2 = getc(X2, ln), v3 = getc(X3, ln);
        int k = 0; float best = v0;                       // first-max (strict >)
        if (v1 > best) { best = v1; k = 1; }
        if (v2 > best) { best = v2; k = 2; }
        if (v3 > best) { best = v3; k = 3; }
        idx[ln] = k;
        setc(ox, ln, best);
    }
    __stcs(out2 + i, ox);

    // ---- Phase 2: bias -> out_bias + partial noms (bis - bi_j) ----
    const float2 I0 = __ldcs(bias + base), I1 = __ldcs(bias + base + o1),
                 I2 = __ldcs(bias + base + o2), I3 = __ldcs(bias + base + o3);
    float nb[2][4];
    float2 obi;
    #pragma unroll
    for (int ln = 0; ln < 2; ln++) {
        float v0 = getc(I0, ln), v1 = getc(I1, ln), v2 = getc(I2, ln), v3 = getc(I3, ln);
        float s = sel4(v0, v1, v2, v3, idx[ln]);
        setc(obi, ln, s);
        nb[ln][0] = s - v0; nb[ln][1] = s - v1; nb[ln][2] = s - v2; nb[ln][3] = s - v3;
    }
    __stcs(out2 + N2 + i, obi);

    // ---- Phase 3: a -> out_a + full noms (nb + (as - a_j)) ----
    const float2 A0 = __ldcs(a + base), A1 = __ldcs(a + base + o1),
                 A2 = __ldcs(a + base + o2), A3 = __ldcs(a + base + o3);
    float2 oa;
    #pragma unroll
    for (int ln = 0; ln < 2; ln++) {
        float v0 = getc(A0, ln), v1 = getc(A1, ln), v2 = getc(A2, ln), v3 = getc(A3, ln);
        float s = sel4(v0, v1, v2, v3, idx[ln]);
        setc(oa, ln, s);
        nb[ln][0] += s - v0; nb[ln][1] += s - v1; nb[ln][2] += s - v2; nb[ln][3] += s - v3;
    }
    __stcs(out2 + 2 * N2 + i, oa);

    // ---- Phase 4: b -> out_b + interval candidates (branchless) ----
    float lloc = -CUDART_INF_F;
    float uloc =  CUDART_INF_F;
    const float2 B0 = __ldcs(b + base), B1 = __ldcs(b + base + o1),
                 B2 = __ldcs(b + base + o2), B3 = __ldcs(b + base + o3);
    float2 ob;
    #pragma unroll
    for (int ln = 0; ln < 2; ln++) {
        float v0 = getc(B0, ln), v1 = getc(B1, ln), v2 = getc(B2, ln), v3 = getc(B3, ln);
        float s = sel4(v0, v1, v2, v3, idx[ln]);
        setc(ob, ln, s);
        float d[4] = { v0 - s, v1 - s, v2 - s, v3 - s };
        #pragma unroll
        for (int j = 0; j < 4; j++) {
            // j==idx: 0/0 -> NaN, but both guards are false, so never used.
            float q = __fdividef(nb[ln][j], d[j]);
            uloc = (d[j] > 0.0f) ? fminf(uloc, q) : uloc;
            lloc = (d[j] < 0.0f) ? fmaxf(lloc, q) : lloc;
        }
    }
    __stcs(out2 + 3 * N2 + i, ob);

    // ---- Block reduction: warp shuffle -> shared -> 3 relaxed atomics ----
    #pragma unroll
    for (int off = 16; off; off >>= 1) {
        lloc = fmaxf(lloc, __shfl_xor_sync(0xffffffffu, lloc, off));
        uloc = fminf(uloc, __shfl_xor_sync(0xffffffffu, uloc, off));
    }
    __shared__ float sl[8], su[8];
    const int warp = threadIdx.x >> 5;
    const int lane = threadIdx.x & 31;
    if (lane == 0) { sl[warp] = lloc; su[warp] = uloc; }
    __syncthreads();
    if (threadIdx.x == 0) {
        float lb = sl[0], ub = su[0];
        #pragma unroll
        for (int w = 1; w < 8; w++) {
            lb = fmaxf(lb, sl[w]);
            ub = fminf(ub, su[w]);
        }
        // Relaxed L2 RMWs; same 128B line as g_count -> same LTS slice,
        // issued in order from this thread. No fences, no acquire, no L1 flush.
        if (lb != -CUDART_INF_F) atomicMaxF(&g_lbits, lb);
        if (ub !=  CUDART_INF_F) atomicMinF(&g_ubits, ub);
        if (atomicAdd(&g_count, 1u) == (unsigned)(NBLK - 1)) {
            // Last arriver: read lattice via relaxed RMWs (L2-coherent, never
            // stale-L1), finalize the two scalars, reset lattice for replay.
            float lf = __uint_as_float(atomicAdd(&g_lbits, 0u));
            float uf = __uint_as_float(atomicAdd(&g_ubits, 0u));
            out[SCAL]     = fmaxf(lin[0], lf);
            out[SCAL + 1] = fminf(uin[0], uf);
            atomicExch(&g_lbits, 0xFF800000u);
            atomicExch(&g_ubits, 0x7F800000u);
            atomicExch(&g_count, 0u);   // kernel boundary orders for next replay
        }
    }
}

extern "C" void kernel_launch(void* const* d_in, const int* in_sizes, int n_in,
                              void* d_out, int out_size) {
    const float2* x  = (const float2*)d_in[0];
    const float2* bi = (const float2*)d_in[1];
    const float2* a  = (const float2*)d_in[2];
    const float2* b  = (const float2*)d_in[3];
    const float*  l  = (const float*)d_in[4];
    const float*  u  = (const float*)d_in[5];
    float* out = (float*)d_out;

    pool_kernel<<<NBLK, 256>>>(x, bi, a, b, l, u, out);   // single kernel
}